// round 10
// baseline (speedup 1.0000x reference)
#include <cuda_runtime.h>
#include <math.h>

#define Nn   1048576
#define Dd   128
#define Gg   4096
#define HID  50
#define GDIM 201
#define TAILC 33
#define OUTC 234   // 201 + 33
#define JPAD 64    // W1t padded rows
#define W2P  204   // W2 padded cols (51 float4s)
#define GPB  4     // groups per fused block

// ---------------- device scratch (no runtime allocation allowed) ----------------
__device__ int   d_start[Gg + 1];       // segment row boundaries
__device__ float d_aggr [Gg * 512];     // [g][mean(128) | std(128) | max(128) | min(128)]
__device__ float d_W1t  [JPAD * 512];   // W1 transposed + padded: [j][k]
__device__ float d_W2p  [HID * W2P];    // W2 padded: [j][204]

// ---------------- kernel 0: segment boundaries via linear boundary scan ----------------
__global__ __launch_bounds__(256) void bounds_kernel(const int* __restrict__ batch) {
    int i = blockIdx.x * 256 + threadIdx.x;          // 0 .. Nn/4-1
    const int4* b4 = reinterpret_cast<const int4*>(batch);
    int4 b = __ldg(&b4[i]);
    int prev = (i == 0) ? -1 : __ldg(&batch[i * 4 - 1]);

    int pos = i * 4;
    for (int g = prev + 1; g <= b.x; g++) d_start[g] = pos;
    for (int g = b.x  + 1; g <= b.y; g++) d_start[g] = pos + 1;
    for (int g = b.y  + 1; g <= b.z; g++) d_start[g] = pos + 2;
    for (int g = b.z  + 1; g <= b.w; g++) d_start[g] = pos + 3;

    if (i == Nn / 4 - 1) {
        for (int g = b.w + 1; g <= Gg; g++) d_start[g] = Nn;
    }
}

// ---------------- kernel 0b: transpose W1 -> [64][512] zero-padded ----------------
__global__ __launch_bounds__(512) void w1t_kernel(const float* __restrict__ W1) {
    int j = blockIdx.x;            // 0..63
    int k = threadIdx.x;           // 0..511
    d_W1t[j * 512 + k] = (j < HID) ? __ldg(&W1[k * HID + j]) : 0.f;
}

// ---------------- kernel 0c: pad W2 [50][201] -> [50][204] ----------------
__global__ __launch_bounds__(256) void w2p_kernel(const float* __restrict__ W2) {
    int j = blockIdx.x;            // 0..49
    int c = threadIdx.x;           // 0..255
    if (c < W2P)
        d_W2p[j * W2P + c] = (c < GDIM) ? __ldg(&W2[j * GDIM + c]) : 0.f;
}

// ---------------- kernel A: one block per segment, software-pipelined loads ----------------
__global__ __launch_bounds__(128) void seg_kernel(const float4* __restrict__ x4) {
    __shared__ __align__(16) float sm_s[512];
    __shared__ __align__(16) float sm_q[512];
    __shared__ __align__(16) float sm_x[512];
    __shared__ __align__(16) float sm_n[512];

    int g    = blockIdx.x;
    int lane = threadIdx.x & 31;
    int w    = threadIdx.x >> 5;

    int lo  = d_start[g];
    int hi  = d_start[g + 1];
    int len = hi - lo;
    int chunk = (len + 3) >> 2;
    int rb = lo + w * chunk;
    int re = min(rb + chunk, hi);
    int nrows = max(re - rb, 0);
    int nit   = nrows >> 2;          // groups of 4 rows

    float4 s  = make_float4(0.f, 0.f, 0.f, 0.f);
    float4 q  = make_float4(0.f, 0.f, 0.f, 0.f);
    float4 mx = make_float4(-INFINITY, -INFINITY, -INFINITY, -INFINITY);
    float4 mn = make_float4( INFINITY,  INFINITY,  INFINITY,  INFINITY);

#define ACC(V)                                                                  \
        s.x += (V).x; s.y += (V).y; s.z += (V).z; s.w += (V).w;                 \
        q.x = fmaf((V).x,(V).x,q.x); q.y = fmaf((V).y,(V).y,q.y);               \
        q.z = fmaf((V).z,(V).z,q.z); q.w = fmaf((V).w,(V).w,q.w);               \
        mx.x = fmaxf(mx.x,(V).x); mx.y = fmaxf(mx.y,(V).y);                     \
        mx.z = fmaxf(mx.z,(V).z); mx.w = fmaxf(mx.w,(V).w);                     \
        mn.x = fminf(mn.x,(V).x); mn.y = fminf(mn.y,(V).y);                     \
        mn.z = fminf(mn.z,(V).z); mn.w = fminf(mn.w,(V).w);

    const float4* p = x4 + (size_t)rb * 32 + lane;

    if (nit > 0) {
        float4 a0 = __ldg(p);
        float4 a1 = __ldg(p + 32);
        float4 a2 = __ldg(p + 64);
        float4 a3 = __ldg(p + 96);
        p += 128;
#pragma unroll 1
        for (int t = 1; t < nit; t++) {
            float4 n0 = __ldg(p);
            float4 n1 = __ldg(p + 32);
            float4 n2 = __ldg(p + 64);
            float4 n3 = __ldg(p + 96);
            p += 128;
            ACC(a0) ACC(a1) ACC(a2) ACC(a3)
            a0 = n0; a1 = n1; a2 = n2; a3 = n3;
        }
        ACC(a0) ACC(a1) ACC(a2) ACC(a3)
    }
    for (int r = rb + nit * 4; r < re; r++) {
        float4 v = __ldg(p);
        p += 32;
        ACC(v)
    }
#undef ACC

    reinterpret_cast<float4*>(sm_s)[w * 32 + lane] = s;
    reinterpret_cast<float4*>(sm_q)[w * 32 + lane] = q;
    reinterpret_cast<float4*>(sm_x)[w * 32 + lane] = mx;
    reinterpret_cast<float4*>(sm_n)[w * 32 + lane] = mn;
    __syncthreads();

    int col = threadIdx.x;   // 0..127: finalize column `col`
    float fs = sm_s[col] + sm_s[128 + col] + sm_s[256 + col] + sm_s[384 + col];
    float fq = sm_q[col] + sm_q[128 + col] + sm_q[256 + col] + sm_q[384 + col];
    float fx = fmaxf(fmaxf(sm_x[col], sm_x[128 + col]), fmaxf(sm_x[256 + col], sm_x[384 + col]));
    float fn = fminf(fminf(sm_n[col], sm_n[128 + col]), fminf(sm_n[256 + col], sm_n[384 + col]));

    float c    = fmaxf((float)len, 1.f);
    float mean = fs / c;
    float var  = fq / c - mean * mean;
    float stdv = sqrtf(fmaxf(var, 0.f) + 1e-5f);

    float* dst = d_aggr + (size_t)g * 512;
    dst[col]        = mean;
    dst[128 + col]  = stdv;
    dst[256 + col]  = fx;
    dst[384 + col]  = fn;
}

// ---------------- kernel B: fused MLP + LayerNorm + head + tail ----------------
// 4 groups per block, 256 threads, 1024 blocks (higher residency).
// GEMM1: warp owns a j-quad per sweep (2 sweeps over JPAD=64); per k-chunk the
// 4 group activations are loaded from smem ONCE (LDS halved vs j-pair), then
// 4 coalesced W1t rows stream over them. GEMM2 uses vectorized LDG.128 on W2p.
__global__ __launch_bounds__(256) void fused_kernel(
    const float* __restrict__ b1,
    const float* __restrict__ lng, const float* __restrict__ lnb,
    const float* __restrict__ b2,
    const float* __restrict__ u, float* __restrict__ out) {

    __shared__ __align__(16) float aggrT[GPB * 512];       // [g][k]
    __shared__ __align__(16) float hraw [GPB * 52];        // [g][j]
    __shared__ __align__(16) float hnT  [HID * GPB + GPB]; // [j][g]

    int tid   = threadIdx.x;
    int lane  = tid & 31;
    int wrp   = tid >> 5;            // 0..7
    int gbase = blockIdx.x * GPB;

    // ---- stage 1: copy aggr rows for 4 groups into smem (coalesced float4) ----
    {
        const float4* src = reinterpret_cast<const float4*>(d_aggr) + (size_t)gbase * 128;
        float4* dst = reinterpret_cast<float4*>(aggrT);
        dst[tid]       = __ldg(&src[tid]);
        dst[tid + 256] = __ldg(&src[tid + 256]);
    }
    __syncthreads();

    // ---- stage 2: GEMM1  h[g][j] = selu(sum_k aggr[g][k]*W1[k][j] + b1[j]) ----
    const float SC = 1.0507009873554805f, AL = 1.6732632423543772f;
#pragma unroll
    for (int sw = 0; sw < 2; sw++) {
        int j0 = wrp * 4 + sw * 32;          // quad j0..j0+3 (< 64, zero-padded)
        float pg[4][4];                       // [j][g]
#pragma unroll
        for (int j = 0; j < 4; j++)
#pragma unroll
            for (int g = 0; g < 4; g++) pg[j][g] = 0.f;

#pragma unroll
        for (int it = 0; it < 4; it++) {
            int k = it * 128 + lane * 4;
            float4 a[4];
#pragma unroll
            for (int g = 0; g < 4; g++)
                a[g] = *reinterpret_cast<const float4*>(&aggrT[g * 512 + k]);
            float4 w[4];
#pragma unroll
            for (int j = 0; j < 4; j++)
                w[j] = __ldg(reinterpret_cast<const float4*>(d_W1t + (j0 + j) * 512 + k));
#pragma unroll
            for (int j = 0; j < 4; j++)
#pragma unroll
                for (int g = 0; g < 4; g++)
                    pg[j][g] = fmaf(w[j].x, a[g].x, fmaf(w[j].y, a[g].y,
                               fmaf(w[j].z, a[g].z, fmaf(w[j].w, a[g].w, pg[j][g]))));
        }
#pragma unroll
        for (int o = 16; o > 0; o >>= 1)
#pragma unroll
            for (int j = 0; j < 4; j++)
#pragma unroll
                for (int g = 0; g < 4; g++)
                    pg[j][g] += __shfl_xor_sync(0xffffffffu, pg[j][g], o);
#pragma unroll
        for (int g = 0; g < 4; g++) {
            if (lane == g) {
#pragma unroll
                for (int j = 0; j < 4; j++) {
                    int jj = j0 + j;
                    if (jj < HID) {
                        float v = pg[j][g] + __ldg(&b1[jj]);
                        hraw[g * 52 + jj] = v > 0.f ? SC * v : SC * AL * expm1f(v);
                    }
                }
            }
        }
    }
    __syncthreads();

    // ---- stage 3: LayerNorm over HID=50, warps 0..3 handle group = wrp ----
    if (wrp < GPB) {
        int g = wrp;
        float v0 = (lane < HID)      ? hraw[g * 52 + lane]      : 0.f;
        float v1 = (lane + 32 < HID) ? hraw[g * 52 + lane + 32] : 0.f;
        float sm  = v0 + v1;
        float sq2 = v0 * v0 + v1 * v1;
#pragma unroll
        for (int o = 16; o > 0; o >>= 1) {
            sm  += __shfl_xor_sync(0xffffffffu, sm,  o);
            sq2 += __shfl_xor_sync(0xffffffffu, sq2, o);
        }
        float mu  = sm * (1.f / HID);
        float var = sq2 * (1.f / HID) - mu * mu;
        float rs  = rsqrtf(var + 1e-5f);
        if (lane < HID)
            hnT[lane * GPB + g] = (v0 - mu) * rs * lng[lane] + lnb[lane];
        if (lane + 32 < HID)
            hnT[(lane + 32) * GPB + g] = (v1 - mu) * rs * lng[lane + 32] + lnb[lane + 32];
    }
    __syncthreads();

    // ---- stage 4: GEMM2  head = hn @ W2 + b2  (thread: 1 group x 4 consecutive cols) ----
    {
        int c  = tid & 63;           // float4 col-block: cols c*4 .. c*4+3
        int gq = tid >> 6;           // 0..3 -> group
        if (c * 4 < W2P) {
            float acc0 = 0.f, acc1 = 0.f, acc2 = 0.f, acc3 = 0.f;
#pragma unroll 5
            for (int j = 0; j < HID; j++) {
                float h = hnT[j * GPB + gq];                      // broadcast LDS
                float4 w4 = __ldg(reinterpret_cast<const float4*>(d_W2p + j * W2P + c * 4));
                acc0 = fmaf(h, w4.x, acc0);
                acc1 = fmaf(h, w4.y, acc1);
                acc2 = fmaf(h, w4.z, acc2);
                acc3 = fmaf(h, w4.w, acc3);
            }
            int g = gbase + gq;
            size_t row = (size_t)g * OUTC;
            int cc = c * 4;
            if (cc + 0 < GDIM) out[row + cc + 0] = acc0 + __ldg(&b2[cc + 0]);
            if (cc + 1 < GDIM) out[row + cc + 1] = acc1 + __ldg(&b2[cc + 1]);
            if (cc + 2 < GDIM) out[row + cc + 2] = acc2 + __ldg(&b2[cc + 2]);
            if (cc + 3 < GDIM) out[row + cc + 3] = acc3 + __ldg(&b2[cc + 3]);
        }
    }

    // ---- stage 5: tail = u[:, -33:] ----
    if (tid < GPB * TAILC) {
        int lg = tid / TAILC;
        int t  = tid % TAILC;
        int g  = gbase + lg;
        out[(size_t)g * OUTC + GDIM + t] = __ldg(&u[g * 64 + 31 + t]);
    }
}

// ---------------- launch ----------------
extern "C" void kernel_launch(void* const* d_in, const int* in_sizes, int n_in,
                              void* d_out, int out_size) {
    const float* x     = (const float*)d_in[0];
    // d_in[1] edge_index, d_in[2] edge_attr: unused by reference
    const float* u     = (const float*)d_in[3];
    const int*   batch = (const int*)  d_in[4];
    const float* W1    = (const float*)d_in[5];
    const float* b1    = (const float*)d_in[6];
    const float* lng   = (const float*)d_in[7];
    const float* lnb   = (const float*)d_in[8];
    const float* W2    = (const float*)d_in[9];
    const float* b2    = (const float*)d_in[10];
    float* out = (float*)d_out;

    bounds_kernel<<<Nn / 4 / 256, 256>>>(batch);
    w1t_kernel<<<JPAD, 512>>>(W1);
    w2p_kernel<<<HID, 256>>>(W2);
    seg_kernel<<<Gg, 128>>>((const float4*)x);
    fused_kernel<<<Gg / GPB, 256>>>(b1, lng, lnb, b2, u, out);
}